// round 4
// baseline (speedup 1.0000x reference)
#include <cuda_runtime.h>

// ---------------------------------------------------------------------------
// SSD post-process, bucketed selection, 3 small kernels:
//  K1 k_scan    : stream conf (8x float4 batched) -> prefilter -> exact softmax
//                 -> emit key into per-score-bin bucket (atomic slot = histogram)
//  K2 k_mid     : 1 block: cutoff bin (warp suffix scan) -> gather bins>=cut
//                 (~550 keys) -> hybrid bitonic sort desc -> decode top-512
//  K3 k_iou_nms : distributed 512x512 suppression bitmask -> [last block]
//                 serial greedy NMS -> output + state reset for next replay
// ---------------------------------------------------------------------------

#define NB       512                // score-bit bins
#define BSHIFT   12                 // 4096-ulp bins
#define BASEBITS 0x3F666666u        // bits(0.9f)
#define CAP      2048               // bucket capacity per bin
#define KTOP     512
#define SELCAP   1024
#define PREF_T   2.19f              // conservative prefilter: ln(9)=2.1972

__device__ __align__(16) int  g_hist[NB];
__device__ unsigned long long g_bucket[NB * CAP];   // 8MB
__device__ unsigned           g_tick3;
__device__ float4             g_box[KTOP];
__device__ float              g_area[KTOP];
__device__ float              g_score[KTOP];
__device__ unsigned           g_mask32[KTOP * 16];

// ---------------------------------------------------------------------------
// K1: each thread handles 8 float4 (16 priors), loads batched for MLP.
// Emission: scattered bucket store, atomics spread over ~410 bins.
// ---------------------------------------------------------------------------
__global__ void __launch_bounds__(256) k_scan(const float4* __restrict__ conf4, int n4) {
    int base = blockIdx.x * 2048 + threadIdx.x;

    float4 v[8];
#pragma unroll
    for (int k = 0; k < 8; ++k) {
        int i = base + k * 256;
        v[k] = (i < n4) ? __ldg(&conf4[i]) : make_float4(0.f, 0.f, 0.f, 0.f);
    }

#pragma unroll
    for (int k = 0; k < 8; ++k) {
#pragma unroll
        for (int e = 0; e < 2; ++e) {
            float c0 = e ? v[k].z : v[k].x;
            float c1 = e ? v[k].w : v[k].y;
            if (c1 - c0 > PREF_T) {
                float s = 1.0f / (1.0f + expf(c0 - c1));   // exact fp32 softmax
                if (s > 0.9f) {
                    unsigned sb  = __float_as_uint(s);
                    unsigned idx = 2u * (unsigned)(base + k * 256) + (unsigned)e;
                    int bin  = (int)((sb - BASEBITS) >> BSHIFT);
                    int slot = atomicAdd(&g_hist[bin], 1);
                    if (slot < CAP)
                        g_bucket[bin * CAP + slot] =
                            ((unsigned long long)sb << 32) |
                            (unsigned long long)(0xffffffffu - idx);
                }
            }
        }
    }
}

// ---------------------------------------------------------------------------
// hybrid bitonic helper (descending, 64-bit keys)
// ---------------------------------------------------------------------------
__device__ __forceinline__ unsigned long long bt_shfl(unsigned long long v, int j,
                                                      int k, int tid) {
    unsigned long long pv = __shfl_xor_sync(0xffffffffu, v, j);
    bool ilow   = (tid & j) == 0;
    bool maxlow = (tid & k) == 0;
    return (ilow == maxlow) ? (v > pv ? v : pv) : (v < pv ? v : pv);
}

// ---------------------------------------------------------------------------
// K2: single block. cutoff -> gather -> sort -> decode.
// ---------------------------------------------------------------------------
__global__ void __launch_bounds__(1024, 1) k_mid(const float4* __restrict__ loc,
                                                 const float4* __restrict__ priors) {
    __shared__ unsigned long long sbuf[SELCAP];
    __shared__ int s_pc[NB];
    __shared__ int s_cut;
    int tid  = threadIdx.x;
    int lane = tid & 31;

    // ---- cutoff: warp 0, shfl suffix scan over 512 bins ----
    if (tid == 0) s_cut = 0;
    if (tid < 32) {
        int cnt[16];
        int acc = 0;
#pragma unroll
        for (int q = 0; q < 4; ++q) {
            int4 h = ((const int4*)g_hist)[tid * 4 + q];
            cnt[q * 4 + 0] = h.x; cnt[q * 4 + 1] = h.y;
            cnt[q * 4 + 2] = h.z; cnt[q * 4 + 3] = h.w;
            acc += h.x + h.y + h.z + h.w;
        }
        int suf = acc;
#pragma unroll
        for (int s = 1; s < 32; s <<= 1) {
            int t = __shfl_down_sync(0xffffffffu, suf, s);
            if (lane + s < 32) suf += t;
        }
        int nsuf = __shfl_down_sync(0xffffffffu, suf, 1);
        if (lane == 31) nsuf = 0;
        if (suf >= KTOP && nsuf < KTOP) {
            int run = nsuf, cb = lane * 16;
#pragma unroll
            for (int r = 15; r >= 0; --r) {
                run += cnt[r];
                if (run >= KTOP) { cb = lane * 16 + r; break; }
            }
            s_cut = cb;
        }
    }
    __syncthreads();
    int cut = s_cut;

    // ---- gather bins >= cut: exclusive prefix over per-bin counts ----
    int c = 0;
    if (tid < NB && tid >= cut) {
        c = g_hist[tid];
        if (c > CAP) c = CAP;
    }
    if (tid < NB) s_pc[tid] = c;
    __syncthreads();
    for (int st = 1; st < NB; st <<= 1) {
        int a = 0;
        if (tid < NB && tid >= st) a = s_pc[tid - st];
        __syncthreads();
        if (tid < NB) s_pc[tid] += a;
        __syncthreads();
    }
    int off = (tid < NB) ? (s_pc[tid] - c) : 0;
    // zero-pad the sort buffer, then scatter gathered keys
    sbuf[tid] = 0ull;
    __syncthreads();
    for (int i = 0; i < c; ++i) {
        int p = off + i;
        if (p < SELCAP) sbuf[p] = g_bucket[tid * CAP + i];
    }
    __syncthreads();

    // ---- hybrid bitonic sort (desc) over 1024 keys ----
    unsigned long long v = sbuf[tid];
#pragma unroll
    for (int k = 2; k <= 32; k <<= 1)
#pragma unroll
        for (int j = k >> 1; j >= 1; j >>= 1)
            v = bt_shfl(v, j, k, tid);
    for (int k = 64; k <= SELCAP; k <<= 1) {
        for (int j = k >> 1; j >= 32; j >>= 1) {
            __syncthreads();
            sbuf[tid] = v;
            __syncthreads();
            unsigned long long pv = sbuf[tid ^ j];
            bool ilow = (tid & j) == 0;
            bool maxlow = (tid & k) == 0;
            v = (ilow == maxlow) ? (v > pv ? v : pv) : (v < pv ? v : pv);
        }
#pragma unroll
        for (int j = 16; j >= 1; j >>= 1)
            v = bt_shfl(v, j, k, tid);
    }

    // ---- decode top-512 ----
    if (tid < KTOP) {
        unsigned long long key = v;
        float X1 = 0.f, Y1 = 0.f, X2 = 0.f, Y2 = 0.f, score = -1.0f;
        if (key != 0ull) {
            score = __uint_as_float((unsigned)(key >> 32));
            unsigned idx = 0xffffffffu - (unsigned)(key & 0xffffffffu);
            float4 l = __ldg(&loc[idx]);
            float4 p = __ldg(&priors[idx]);
            float cx = __fadd_rn(p.x, __fmul_rn(__fmul_rn(l.x, 0.1f), p.z));
            float cy = __fadd_rn(p.y, __fmul_rn(__fmul_rn(l.y, 0.1f), p.w));
            float w  = __fmul_rn(p.z, expf(__fmul_rn(l.z, 0.2f)));
            float h  = __fmul_rn(p.w, expf(__fmul_rn(l.w, 0.2f)));
            float x1 = __fsub_rn(cx, __fmul_rn(w, 0.5f));
            float y1 = __fsub_rn(cy, __fmul_rn(h, 0.5f));
            float x2 = __fadd_rn(x1, w);
            float y2 = __fadd_rn(y1, h);
            X1 = __fmul_rn(x1, 2048.0f);
            Y1 = __fmul_rn(y1, 2048.0f);
            X2 = __fmul_rn(x2, 2048.0f);
            Y2 = __fmul_rn(y2, 2048.0f);
        }
        g_box[tid]   = make_float4(X1, Y1, X2, Y2);
        g_area[tid]  = __fmul_rn(__fadd_rn(__fsub_rn(X2, X1), 1.0f),
                                 __fadd_rn(__fsub_rn(Y2, Y1), 1.0f));
        g_score[tid] = score;
    }
}

// ---------------------------------------------------------------------------
// K3: distributed suppression bitmask; last block does serial NMS + output
// + full state reset for the next graph replay.
// ---------------------------------------------------------------------------
__global__ void __launch_bounds__(256) k_iou_nms(float* __restrict__ out) {
    int tid = threadIdx.x;
    int T   = blockIdx.x * 256 + tid;     // 0..32767
    {
        int i  = T >> 6;
        int j0 = (T & 63) << 3;
        unsigned bits = 0u;
        float si = g_score[i];
        if (si > 0.0f) {
            float4 bi = g_box[i];
            float  ai = g_area[i];
#pragma unroll
            for (int b = 0; b < 8; ++b) {
                int j = j0 + b;
                float4 bj = g_box[j];
                float xx1 = fmaxf(bi.x, bj.x);
                float yy1 = fmaxf(bi.y, bj.y);
                float xx2 = fminf(bi.z, bj.z);
                float yy2 = fminf(bi.w, bj.w);
                float w = fmaxf(__fadd_rn(__fsub_rn(xx2, xx1), 1.0f), 0.0f);
                float h = fmaxf(__fadd_rn(__fsub_rn(yy2, yy1), 1.0f), 0.0f);
                float inter = __fmul_rn(w, h);
                float uni = __fsub_rn(__fadd_rn(ai, g_area[j]), inter);
                if (j > i && inter > __fmul_rn(0.4f, uni)) bits |= 1u << b;
            }
        }
        ((unsigned char*)g_mask32)[T] = (unsigned char)bits;
    }

    __threadfence();
    __shared__ int s_last;
    __syncthreads();
    if (tid == 0) s_last = (atomicAdd(&g_tick3, 1u) == gridDim.x - 1) ? 1 : 0;
    __syncthreads();
    if (!s_last) return;

    // ---- last block: serial greedy NMS + output + reset ----
    __shared__ unsigned um[KTOP * 16];    // 32KB
    __shared__ unsigned s_keepw[16];
    for (int w = tid; w < KTOP * 16; w += 256) um[w] = g_mask32[w];
    __syncthreads();

    if (tid < 32) {
        unsigned rem = 0u;                // lanes 0..15 own column words
        for (int c = 0; c < 16; ++c) {
            unsigned val = __shfl_sync(0xffffffffu, rem, c);
            unsigned dm[32];
#pragma unroll
            for (int r = 0; r < 32; ++r) dm[r] = um[(c * 32 + r) * 16 + c];
#pragma unroll
            for (int r = 0; r < 32; ++r)
                if (!((val >> r) & 1u)) val |= dm[r];
            unsigned keep = ~val;
            if (tid < 16) {
#pragma unroll
                for (int r = 0; r < 32; ++r)
                    if ((keep >> r) & 1u) rem |= um[(c * 32 + r) * 16 + tid];
            }
        }
        if (tid < 16) s_keepw[tid] = rem;
    }
    __syncthreads();

    const float inv = 1.0f / 2048.0f;     // exact
    for (int r = tid; r < KTOP; r += 256) {
        float sc = g_score[r];
        bool kept = (sc > 0.0f) && !((s_keepw[r >> 5] >> (r & 31)) & 1u);
        float4 b = g_box[r];
        out[r * 5 + 0] = kept ? __fmul_rn(b.x, inv) : 0.0f;
        out[r * 5 + 1] = kept ? __fmul_rn(b.y, inv) : 0.0f;
        out[r * 5 + 2] = kept ? __fmul_rn(b.z, inv) : 0.0f;
        out[r * 5 + 3] = kept ? __fmul_rn(b.w, inv) : 0.0f;
        out[r * 5 + 4] = kept ? sc : 0.0f;
    }

    // tail reset for next graph replay (globals zero-initialized at load)
    for (int i = tid; i < NB; i += 256) g_hist[i] = 0;
    if (tid == 0) g_tick3 = 0u;
}

// ---------------------------------------------------------------------------
extern "C" void kernel_launch(void* const* d_in, const int* in_sizes, int n_in,
                              void* d_out, int out_size) {
    const float4* loc    = (const float4*)d_in[0];   // [N,4]
    const float4* conf4  = (const float4*)d_in[1];   // [N,2] as float4 pairs
    const float4* priors = (const float4*)d_in[2];   // [N,4]
    float* out = (float*)d_out;                      // [512,5]
    int n  = in_sizes[0] / 4;
    int n4 = n >> 1;

    k_scan<<<(n4 + 2047) / 2048, 256>>>(conf4, n4);
    k_mid<<<1, 1024>>>(loc, priors);
    k_iou_nms<<<128, 256>>>(out);
}

// round 5
// speedup vs baseline: 1.5481x; 1.5481x over previous
#include <cuda_runtime.h>

// ---------------------------------------------------------------------------
// SSD post-process, 2 kernels:
//  K1 k_scan_mid : stream conf (interleaved load/ballot/shared staging, the
//                  measured-fast structure) -> epilogue buckets keys by score
//                  bin (atomics OFF the stream path) -> [last block via tick]
//                  cutoff suffix-scan -> gather bins>=cut (~550 keys) ->
//                  hybrid bitonic sort desc -> decode top-512 boxes
//  K2 k_iou_nms  : distributed 512x512 suppression bitmask -> [last block]
//                  serial greedy NMS -> output + state reset for next replay
// ---------------------------------------------------------------------------

#define NB2      16384              // score-bit bins (128-ulp)
#define BSHIFT   7
#define BASEBITS 0x3F666666u        // bits(0.9f)
#define CAP      128                // bucket capacity per bin (max bin ~30)
#define KTOP     512
#define SELCAP   1024
#define PREF_T   2.19f              // conservative prefilter: ln(9)=2.1972

__device__ __align__(16) int  g_hist[NB2];
__device__ unsigned long long g_bucket[NB2 * CAP];   // 16MB
__device__ unsigned           g_tick1;
__device__ unsigned           g_tick3;
__device__ float4             g_box[KTOP];
__device__ float              g_area[KTOP];
__device__ float              g_score[KTOP];
__device__ unsigned           g_mask32[KTOP * 16];

// hybrid bitonic helper (descending, 64-bit keys)
__device__ __forceinline__ unsigned long long bt_shfl(unsigned long long v, int j,
                                                      int k, int tid) {
    unsigned long long pv = __shfl_xor_sync(0xffffffffu, v, j);
    bool ilow   = (tid & j) == 0;
    bool maxlow = (tid & k) == 0;
    return (ilow == maxlow) ? (v > pv ? v : pv) : (v < pv ? v : pv);
}

// ---------------------------------------------------------------------------
// K1: grid 256 x 1024 threads; each block covers 4096 conf-float4 (8192 priors)
// ---------------------------------------------------------------------------
__global__ void __launch_bounds__(1024, 1)
k_scan_mid(const float4* __restrict__ conf4, int n4,
           const float4* __restrict__ loc, const float4* __restrict__ priors) {
    __shared__ unsigned long long lbuf[2048];     // staged keys (exp ~500/block)
    __shared__ unsigned long long sbuf[SELCAP];   // sort exchange (last block)
    __shared__ int s_wtot[32], s_wsuf[32];
    __shared__ int lcount, s_cut, s_n, s_last;
    int tid  = threadIdx.x;
    int lane = tid & 31;
    int wid  = tid >> 5;
    unsigned lt = (1u << lane) - 1u;
    if (tid == 0) lcount = 0;
    __syncthreads();

    // ---- streaming scan (round-2 structure: interleaved, ballot-staged) ----
    int base = blockIdx.x * 4096 + tid;
#pragma unroll
    for (int k = 0; k < 4; ++k) {
        int i4 = base + k * 1024;
        bool p0 = false, p1 = false;
        float s0 = 0.f, s1 = 0.f;
        if (i4 < n4) {
            float4 c = conf4[i4];
            if (c.y - c.x > PREF_T) {
                s0 = 1.0f / (1.0f + expf(c.x - c.y));    // exact fp32 softmax
                p0 = s0 > 0.9f;
            }
            if (c.w - c.z > PREF_T) {
                s1 = 1.0f / (1.0f + expf(c.z - c.w));
                p1 = s1 > 0.9f;
            }
        }
        unsigned m0 = __ballot_sync(0xffffffffu, p0);
        unsigned m1 = __ballot_sync(0xffffffffu, p1);
        int cnt = __popc(m0) + __popc(m1);
        if (cnt) {
            int b0 = 0;
            if (lane == 0) b0 = atomicAdd(&lcount, cnt);
            b0 = __shfl_sync(0xffffffffu, b0, 0);
            if (p0) {
                unsigned sb  = __float_as_uint(s0);
                unsigned idx = 2u * (unsigned)i4;
                lbuf[b0 + __popc(m0 & lt)] =
                    ((unsigned long long)sb << 32) |
                    (unsigned long long)(0xffffffffu - idx);
            }
            if (p1) {
                unsigned sb  = __float_as_uint(s1);
                unsigned idx = 2u * (unsigned)i4 + 1u;
                lbuf[b0 + __popc(m0) + __popc(m1 & lt)] =
                    ((unsigned long long)sb << 32) |
                    (unsigned long long)(0xffffffffu - idx);
            }
        }
    }
    __syncthreads();

    // ---- epilogue: bucket staged keys (atomics off the stream path) ----
    int lc = lcount;
    if (lc > 2048) lc = 2048;
    for (int j = tid; j < lc; j += 1024) {
        unsigned long long key = lbuf[j];
        int bin  = (int)(((unsigned)(key >> 32) - BASEBITS) >> BSHIFT);
        int slot = atomicAdd(&g_hist[bin], 1);
        if (slot < CAP) g_bucket[bin * CAP + slot] = key;
    }
    __threadfence();
    __syncthreads();
    if (tid == 0) s_last = (atomicAdd(&g_tick1, 1u) == gridDim.x - 1) ? 1 : 0;
    __syncthreads();
    if (!s_last) return;

    // =================== last block: cutoff + gather + sort + decode =======
    // each thread owns 16 bins [16*tid, 16*tid+16)
    int cnt16[16];
    int part = 0;
#pragma unroll
    for (int q = 0; q < 4; ++q) {
        int4 h = ((const int4*)g_hist)[tid * 4 + q];
        cnt16[q * 4 + 0] = h.x; cnt16[q * 4 + 1] = h.y;
        cnt16[q * 4 + 2] = h.z; cnt16[q * 4 + 3] = h.w;
        part += h.x + h.y + h.z + h.w;
    }
    // warp suffix scan of per-thread sums
    int suf = part;
#pragma unroll
    for (int s = 1; s < 32; s <<= 1) {
        int t = __shfl_down_sync(0xffffffffu, suf, s);
        if (lane + s < 32) suf += t;
    }
    if (lane == 0) s_wtot[wid] = suf;     // warp total
    if (tid == 0) { s_cut = 0; s_n = 0; }
    __syncthreads();
    if (wid == 0) {
        int ws = s_wtot[lane];
#pragma unroll
        for (int s = 1; s < 32; s <<= 1) {
            int t = __shfl_down_sync(0xffffffffu, ws, s);
            if (lane + s < 32) ws += t;
        }
        s_wsuf[lane] = ws;                // suffix of warp totals (incl own)
    }
    __syncthreads();
    int S     = suf + ((wid < 31) ? s_wsuf[wid + 1] : 0);  // suffix incl my bins
    int Snext = S - part;                                   // suffix after mine
    if (S >= KTOP && Snext < KTOP) {
        int run = Snext;
#pragma unroll
        for (int r = 15; r >= 0; --r) {
            run += cnt16[r];
            if (run >= KTOP) { s_cut = tid * 16 + r; break; }
        }
    }
    sbuf[tid] = 0ull;                     // zero-pad sort buffer
    __syncthreads();
    int cut = s_cut;

    // gather bins >= cut (order irrelevant; sort fixes it; keys unique)
    int cc[16];
    int tc = 0;
#pragma unroll
    for (int r = 0; r < 16; ++r) {
        int b = tid * 16 + r;
        int c = (b >= cut) ? cnt16[r] : 0;
        if (c > CAP) c = CAP;
        cc[r] = c;
        tc += c;
    }
    int off = 0;
    if (tc) off = atomicAdd(&s_n, tc);
#pragma unroll
    for (int r = 0; r < 16; ++r) {
        int b = tid * 16 + r;
        for (int i = 0; i < cc[r]; ++i) {
            if (off < SELCAP) sbuf[off] = g_bucket[b * CAP + i];
            ++off;
        }
    }
    __syncthreads();

    // hybrid bitonic sort (desc) over 1024 keys
    unsigned long long v = sbuf[tid];
#pragma unroll
    for (int k = 2; k <= 32; k <<= 1)
#pragma unroll
        for (int j = k >> 1; j >= 1; j >>= 1)
            v = bt_shfl(v, j, k, tid);
    for (int k = 64; k <= SELCAP; k <<= 1) {
        for (int j = k >> 1; j >= 32; j >>= 1) {
            __syncthreads();
            sbuf[tid] = v;
            __syncthreads();
            unsigned long long pv = sbuf[tid ^ j];
            bool ilow = (tid & j) == 0;
            bool maxlow = (tid & k) == 0;
            v = (ilow == maxlow) ? (v > pv ? v : pv) : (v < pv ? v : pv);
        }
#pragma unroll
        for (int j = 16; j >= 1; j >>= 1)
            v = bt_shfl(v, j, k, tid);
    }

    // decode top-512
    if (tid < KTOP) {
        unsigned long long key = v;
        float X1 = 0.f, Y1 = 0.f, X2 = 0.f, Y2 = 0.f, score = -1.0f;
        if (key != 0ull) {
            score = __uint_as_float((unsigned)(key >> 32));
            unsigned idx = 0xffffffffu - (unsigned)(key & 0xffffffffu);
            float4 l = __ldg(&loc[idx]);
            float4 p = __ldg(&priors[idx]);
            float cx = __fadd_rn(p.x, __fmul_rn(__fmul_rn(l.x, 0.1f), p.z));
            float cy = __fadd_rn(p.y, __fmul_rn(__fmul_rn(l.y, 0.1f), p.w));
            float w  = __fmul_rn(p.z, expf(__fmul_rn(l.z, 0.2f)));
            float h  = __fmul_rn(p.w, expf(__fmul_rn(l.w, 0.2f)));
            float x1 = __fsub_rn(cx, __fmul_rn(w, 0.5f));
            float y1 = __fsub_rn(cy, __fmul_rn(h, 0.5f));
            float x2 = __fadd_rn(x1, w);
            float y2 = __fadd_rn(y1, h);
            X1 = __fmul_rn(x1, 2048.0f);
            Y1 = __fmul_rn(y1, 2048.0f);
            X2 = __fmul_rn(x2, 2048.0f);
            Y2 = __fmul_rn(y2, 2048.0f);
        }
        g_box[tid]   = make_float4(X1, Y1, X2, Y2);
        g_area[tid]  = __fmul_rn(__fadd_rn(__fsub_rn(X2, X1), 1.0f),
                                 __fadd_rn(__fsub_rn(Y2, Y1), 1.0f));
        g_score[tid] = score;
    }
}

// ---------------------------------------------------------------------------
// K2: distributed suppression bitmask; last block: serial NMS + output + reset
// ---------------------------------------------------------------------------
__global__ void __launch_bounds__(256) k_iou_nms(float* __restrict__ out) {
    int tid = threadIdx.x;
    int T   = blockIdx.x * 256 + tid;     // 0..32767
    {
        int i  = T >> 6;
        int j0 = (T & 63) << 3;
        unsigned bits = 0u;
        float si = g_score[i];
        if (si > 0.0f) {
            float4 bi = g_box[i];
            float  ai = g_area[i];
#pragma unroll
            for (int b = 0; b < 8; ++b) {
                int j = j0 + b;
                float4 bj = g_box[j];
                float xx1 = fmaxf(bi.x, bj.x);
                float yy1 = fmaxf(bi.y, bj.y);
                float xx2 = fminf(bi.z, bj.z);
                float yy2 = fminf(bi.w, bj.w);
                float w = fmaxf(__fadd_rn(__fsub_rn(xx2, xx1), 1.0f), 0.0f);
                float h = fmaxf(__fadd_rn(__fsub_rn(yy2, yy1), 1.0f), 0.0f);
                float inter = __fmul_rn(w, h);
                float uni = __fsub_rn(__fadd_rn(ai, g_area[j]), inter);
                if (j > i && inter > __fmul_rn(0.4f, uni)) bits |= 1u << b;
            }
        }
        ((unsigned char*)g_mask32)[T] = (unsigned char)bits;
    }

    __threadfence();
    __shared__ int s_last;
    __syncthreads();
    if (tid == 0) s_last = (atomicAdd(&g_tick3, 1u) == gridDim.x - 1) ? 1 : 0;
    __syncthreads();
    if (!s_last) return;

    // ---- last block: serial greedy NMS + output + full state reset ----
    __shared__ unsigned um[KTOP * 16];    // 32KB
    __shared__ unsigned s_keepw[16];
    for (int w = tid; w < KTOP * 16; w += 256) um[w] = g_mask32[w];
    __syncthreads();

    if (tid < 32) {
        unsigned rem = 0u;                // lanes 0..15 own column words
        for (int c = 0; c < 16; ++c) {
            unsigned val = __shfl_sync(0xffffffffu, rem, c);
            unsigned dm[32];
#pragma unroll
            for (int r = 0; r < 32; ++r) dm[r] = um[(c * 32 + r) * 16 + c];
#pragma unroll
            for (int r = 0; r < 32; ++r)
                if (!((val >> r) & 1u)) val |= dm[r];
            unsigned keep = ~val;
            if (tid < 16) {
#pragma unroll
                for (int r = 0; r < 32; ++r)
                    if ((keep >> r) & 1u) rem |= um[(c * 32 + r) * 16 + tid];
            }
        }
        if (tid < 16) s_keepw[tid] = rem;
    }
    __syncthreads();

    const float inv = 1.0f / 2048.0f;     // exact
    for (int r = tid; r < KTOP; r += 256) {
        float sc = g_score[r];
        bool kept = (sc > 0.0f) && !((s_keepw[r >> 5] >> (r & 31)) & 1u);
        float4 b = g_box[r];
        out[r * 5 + 0] = kept ? __fmul_rn(b.x, inv) : 0.0f;
        out[r * 5 + 1] = kept ? __fmul_rn(b.y, inv) : 0.0f;
        out[r * 5 + 2] = kept ? __fmul_rn(b.z, inv) : 0.0f;
        out[r * 5 + 3] = kept ? __fmul_rn(b.w, inv) : 0.0f;
        out[r * 5 + 4] = kept ? sc : 0.0f;
    }

    // tail reset for the next graph replay (globals zero-initialized at load)
    for (int i = tid; i < NB2; i += 256) g_hist[i] = 0;
    if (tid == 0) { g_tick1 = 0u; g_tick3 = 0u; }
}

// ---------------------------------------------------------------------------
extern "C" void kernel_launch(void* const* d_in, const int* in_sizes, int n_in,
                              void* d_out, int out_size) {
    const float4* loc    = (const float4*)d_in[0];   // [N,4]
    const float4* conf4  = (const float4*)d_in[1];   // [N,2] as float4 pairs
    const float4* priors = (const float4*)d_in[2];   // [N,4]
    float* out = (float*)d_out;                      // [512,5]
    int n  = in_sizes[0] / 4;
    int n4 = n >> 1;

    k_scan_mid<<<(n4 + 4095) / 4096, 1024>>>(conf4, n4, loc, priors);
    k_iou_nms<<<128, 256>>>(out);
}

// round 7
// speedup vs baseline: 1.6721x; 1.0801x over previous
#include <cuda_runtime.h>

// ---------------------------------------------------------------------------
// SSD post-process, 4 lean kernels (launch boundaries = barriers, no fences):
//  K1 k_scan : stream conf, branchy prefilter (94% reject = 8 instr/16B),
//              shared-atomic staging, epilogue buckets keys by 128-ulp score bin
//  K2 k_mid  : 1 block: cutoff suffix-scan over 16K bins -> gather bins>=cut
//              (~550 keys) -> hybrid bitonic sort desc -> decode top-512
//  K3 k_iou  : 128x256: 512x512 suppression bitmask (pure, no join)
//  K4 k_nms  : 1 block: greedy NMS (register intra-chunk + OR-tree cross-chunk)
//              -> output -> histogram reset for next graph replay
// ---------------------------------------------------------------------------

#define NB2      16384              // score-bit bins (128-ulp)
#define BSHIFT   7
#define BASEBITS 0x3F666666u        // bits(0.9f)
#define CAP      128                // per-bin bucket capacity (max seen ~30)
#define KTOP     512
#define SELCAP   1024
#define PREF_T   2.19f              // conservative prefilter: ln(9)=2.1972

__device__ __align__(16) int  g_hist[NB2];
__device__ unsigned long long g_bucket[NB2 * CAP];   // 16MB
__device__ float4             g_box[KTOP];
__device__ float              g_area[KTOP];
__device__ float              g_score[KTOP];
__device__ unsigned           g_mask32[KTOP * 16];

// ---------------------------------------------------------------------------
// K1: 256 threads/block, 2048 float4 (4096 priors) per block, grid 512.
// ---------------------------------------------------------------------------
__global__ void __launch_bounds__(256) k_scan(const float4* __restrict__ conf4, int n4) {
    __shared__ unsigned long long lbuf[4096];   // full worst-case coverage (32KB)
    __shared__ int lcount;
    int tid = threadIdx.x;
    if (tid == 0) lcount = 0;
    __syncthreads();

    int base = blockIdx.x * 2048 + tid;
#pragma unroll
    for (int k = 0; k < 8; ++k) {
        int i4 = base + k * 256;
        if (i4 < n4) {
            float4 c = conf4[i4];
            if (c.y - c.x > PREF_T) {                       // rare (~6%)
                float s = 1.0f / (1.0f + expf(c.x - c.y));  // exact fp32 softmax
                if (s > 0.9f) {
                    unsigned idx = 2u * (unsigned)i4;
                    int pos = atomicAdd(&lcount, 1);
                    lbuf[pos] = ((unsigned long long)__float_as_uint(s) << 32) |
                                (unsigned long long)(0xffffffffu - idx);
                }
            }
            if (c.w - c.z > PREF_T) {
                float s = 1.0f / (1.0f + expf(c.z - c.w));
                if (s > 0.9f) {
                    unsigned idx = 2u * (unsigned)i4 + 1u;
                    int pos = atomicAdd(&lcount, 1);
                    lbuf[pos] = ((unsigned long long)__float_as_uint(s) << 32) |
                                (unsigned long long)(0xffffffffu - idx);
                }
            }
        }
    }
    __syncthreads();

    // epilogue: scatter staged keys into score-binned buckets (off stream path)
    int lc = lcount;
    for (int j = tid; j < lc; j += 256) {
        unsigned long long key = lbuf[j];
        int bin  = (int)(((unsigned)(key >> 32) - BASEBITS) >> BSHIFT);
        int slot = atomicAdd(&g_hist[bin], 1);
        if (slot < CAP) g_bucket[bin * CAP + slot] = key;
    }
}

// hybrid bitonic helper (descending, 64-bit keys)
__device__ __forceinline__ unsigned long long bt_shfl(unsigned long long v, int j,
                                                      int k, int tid) {
    unsigned long long pv = __shfl_xor_sync(0xffffffffu, v, j);
    bool ilow   = (tid & j) == 0;
    bool maxlow = (tid & k) == 0;
    return (ilow == maxlow) ? (v > pv ? v : pv) : (v < pv ? v : pv);
}

// ---------------------------------------------------------------------------
// K2: single block of 1024: cutoff -> gather -> sort -> decode.
// ---------------------------------------------------------------------------
__global__ void __launch_bounds__(1024, 1) k_mid(const float4* __restrict__ loc,
                                                 const float4* __restrict__ priors) {
    __shared__ unsigned long long sbuf[SELCAP];
    __shared__ int s_wtot[32], s_wsuf[32];
    __shared__ int s_cut, s_n;
    int tid  = threadIdx.x;
    int lane = tid & 31;
    int wid  = tid >> 5;

    // each thread owns 16 bins [16*tid, 16*tid+16)
    int cnt16[16];
    int part = 0;
#pragma unroll
    for (int q = 0; q < 4; ++q) {
        int4 h = ((const int4*)g_hist)[tid * 4 + q];
        cnt16[q * 4 + 0] = h.x; cnt16[q * 4 + 1] = h.y;
        cnt16[q * 4 + 2] = h.z; cnt16[q * 4 + 3] = h.w;
        part += h.x + h.y + h.z + h.w;
    }
    int suf = part;
#pragma unroll
    for (int s = 1; s < 32; s <<= 1) {
        int t = __shfl_down_sync(0xffffffffu, suf, s);
        if (lane + s < 32) suf += t;
    }
    if (lane == 0) s_wtot[wid] = suf;
    if (tid == 0) { s_cut = 0; s_n = 0; }
    __syncthreads();
    if (wid == 0) {
        int ws = s_wtot[lane];
#pragma unroll
        for (int s = 1; s < 32; s <<= 1) {
            int t = __shfl_down_sync(0xffffffffu, ws, s);
            if (lane + s < 32) ws += t;
        }
        s_wsuf[lane] = ws;
    }
    __syncthreads();
    int S     = suf + ((wid < 31) ? s_wsuf[wid + 1] : 0);
    int Snext = S - part;
    if (S >= KTOP && Snext < KTOP) {
        int run = Snext;
#pragma unroll
        for (int r = 15; r >= 0; --r) {
            run += cnt16[r];
            if (run >= KTOP) { s_cut = tid * 16 + r; break; }
        }
    }
    sbuf[tid] = 0ull;
    __syncthreads();
    int cut = s_cut;

    // gather bins >= cut (order irrelevant, the sort fixes it)
    int cc[16];
    int tc = 0;
#pragma unroll
    for (int r = 0; r < 16; ++r) {
        int b = tid * 16 + r;
        int c = (b >= cut) ? cnt16[r] : 0;
        if (c > CAP) c = CAP;
        cc[r] = c;
        tc += c;
    }
    int off = 0;
    if (tc) off = atomicAdd(&s_n, tc);
#pragma unroll
    for (int r = 0; r < 16; ++r) {
        int b = tid * 16 + r;
        for (int i = 0; i < cc[r]; ++i) {
            if (off < SELCAP) sbuf[off] = g_bucket[b * CAP + i];
            ++off;
        }
    }
    __syncthreads();

    // hybrid bitonic sort (desc) over 1024 keys
    unsigned long long v = sbuf[tid];
#pragma unroll
    for (int k = 2; k <= 32; k <<= 1)
#pragma unroll
        for (int j = k >> 1; j >= 1; j >>= 1)
            v = bt_shfl(v, j, k, tid);
    for (int k = 64; k <= SELCAP; k <<= 1) {
        for (int j = k >> 1; j >= 32; j >>= 1) {
            __syncthreads();
            sbuf[tid] = v;
            __syncthreads();
            unsigned long long pv = sbuf[tid ^ j];
            bool ilow = (tid & j) == 0;
            bool maxlow = (tid & k) == 0;
            v = (ilow == maxlow) ? (v > pv ? v : pv) : (v < pv ? v : pv);
        }
#pragma unroll
        for (int j = 16; j >= 1; j >>= 1)
            v = bt_shfl(v, j, k, tid);
    }

    // decode top-512
    if (tid < KTOP) {
        unsigned long long key = v;
        float X1 = 0.f, Y1 = 0.f, X2 = 0.f, Y2 = 0.f, score = -1.0f;
        if (key != 0ull) {
            score = __uint_as_float((unsigned)(key >> 32));
            unsigned idx = 0xffffffffu - (unsigned)(key & 0xffffffffu);
            float4 l = __ldg(&loc[idx]);
            float4 p = __ldg(&priors[idx]);
            float cx = __fadd_rn(p.x, __fmul_rn(__fmul_rn(l.x, 0.1f), p.z));
            float cy = __fadd_rn(p.y, __fmul_rn(__fmul_rn(l.y, 0.1f), p.w));
            float w  = __fmul_rn(p.z, expf(__fmul_rn(l.z, 0.2f)));
            float h  = __fmul_rn(p.w, expf(__fmul_rn(l.w, 0.2f)));
            float x1 = __fsub_rn(cx, __fmul_rn(w, 0.5f));
            float y1 = __fsub_rn(cy, __fmul_rn(h, 0.5f));
            float x2 = __fadd_rn(x1, w);
            float y2 = __fadd_rn(y1, h);
            X1 = __fmul_rn(x1, 2048.0f);
            Y1 = __fmul_rn(y1, 2048.0f);
            X2 = __fmul_rn(x2, 2048.0f);
            Y2 = __fmul_rn(y2, 2048.0f);
        }
        g_box[tid]   = make_float4(X1, Y1, X2, Y2);
        g_area[tid]  = __fmul_rn(__fadd_rn(__fsub_rn(X2, X1), 1.0f),
                                 __fadd_rn(__fsub_rn(Y2, Y1), 1.0f));
        g_score[tid] = score;
    }
}

// ---------------------------------------------------------------------------
// K3: 512x512 suppression bitmask; no join, launch boundary is the barrier.
// ---------------------------------------------------------------------------
__global__ void __launch_bounds__(256) k_iou() {
    int T  = blockIdx.x * 256 + threadIdx.x;   // 0..32767
    int i  = T >> 6;
    int j0 = (T & 63) << 3;
    unsigned bits = 0u;
    float si = g_score[i];
    if (si > 0.0f) {
        float4 bi = g_box[i];
        float  ai = g_area[i];
#pragma unroll
        for (int b = 0; b < 8; ++b) {
            int j = j0 + b;
            float4 bj = g_box[j];
            float xx1 = fmaxf(bi.x, bj.x);
            float yy1 = fmaxf(bi.y, bj.y);
            float xx2 = fminf(bi.z, bj.z);
            float yy2 = fminf(bi.w, bj.w);
            float w = fmaxf(__fadd_rn(__fsub_rn(xx2, xx1), 1.0f), 0.0f);
            float h = fmaxf(__fadd_rn(__fsub_rn(yy2, yy1), 1.0f), 0.0f);
            float inter = __fmul_rn(w, h);
            float uni = __fsub_rn(__fadd_rn(ai, g_area[j]), inter);
            if (j > i && inter > __fmul_rn(0.4f, uni)) bits |= 1u << b;
        }
    }
    ((unsigned char*)g_mask32)[T] = (unsigned char)bits;
}

// ---------------------------------------------------------------------------
// K4: single block of 512: greedy NMS + output + histogram reset.
// ---------------------------------------------------------------------------
__global__ void __launch_bounds__(512, 1) k_nms(float* __restrict__ out) {
    __shared__ unsigned um[KTOP * 16];    // 32KB suppression matrix
    __shared__ unsigned s_keepw[16];
    int tid = threadIdx.x;
    for (int w = tid; w < KTOP * 16; w += 512) um[w] = g_mask32[w];
    __syncthreads();

    if (tid < 32) {
        int wlo = tid & 15;               // lanes 0..15 own column words
        unsigned rem = 0u;
        for (int c = 0; c < 16; ++c) {
            unsigned val = __shfl_sync(0xffffffffu, rem, c);
            // intra-chunk 32x32 closure, all lanes redundantly in registers
            unsigned dm[32];
#pragma unroll
            for (int r = 0; r < 32; ++r) dm[r] = um[(c * 32 + r) * 16 + c];
#pragma unroll
            for (int r = 0; r < 32; ++r)
                if (!((val >> r) & 1u)) val |= dm[r];
            unsigned keep = ~val;
            // cross-chunk: all 32 loads issued independently, predicated OR-tree
            unsigned acc = 0u;
#pragma unroll
            for (int r = 0; r < 32; ++r) {
                unsigned m = um[(c * 32 + r) * 16 + wlo];
                acc |= ((keep >> r) & 1u) ? m : 0u;
            }
            if (tid < 16) rem |= acc;
        }
        if (tid < 16) s_keepw[tid] = rem;
    }
    __syncthreads();

    const float inv = 1.0f / 2048.0f;     // exact
    if (tid < KTOP) {
        int r = tid;
        float sc = g_score[r];
        bool kept = (sc > 0.0f) && !((s_keepw[r >> 5] >> (r & 31)) & 1u);
        float4 b = g_box[r];
        out[r * 5 + 0] = kept ? __fmul_rn(b.x, inv) : 0.0f;
        out[r * 5 + 1] = kept ? __fmul_rn(b.y, inv) : 0.0f;
        out[r * 5 + 2] = kept ? __fmul_rn(b.z, inv) : 0.0f;
        out[r * 5 + 3] = kept ? __fmul_rn(b.w, inv) : 0.0f;
        out[r * 5 + 4] = kept ? sc : 0.0f;
    }

    // histogram reset for the next graph replay (zero-initialized at load)
    for (int i = tid; i < NB2; i += 512) g_hist[i] = 0;
}

// ---------------------------------------------------------------------------
extern "C" void kernel_launch(void* const* d_in, const int* in_sizes, int n_in,
                              void* d_out, int out_size) {
    const float4* loc    = (const float4*)d_in[0];   // [N,4]
    const float4* conf4  = (const float4*)d_in[1];   // [N,2] as float4 pairs
    const float4* priors = (const float4*)d_in[2];   // [N,4]
    float* out = (float*)d_out;                      // [512,5]
    int n  = in_sizes[0] / 4;
    int n4 = n >> 1;

    k_scan<<<(n4 + 2047) / 2048, 256>>>(conf4, n4);
    k_mid<<<1, 1024>>>(loc, priors);
    k_iou<<<128, 256>>>();
    k_nms<<<1, 512>>>(out);
}

// round 8
// speedup vs baseline: 1.6887x; 1.0099x over previous
#include <cuda_runtime.h>

// ---------------------------------------------------------------------------
// SSD post-process, 4 lean kernels (launch boundaries = barriers, no fences):
//  K1 k_scan : stream conf, branchy prefilter, shared staging, bucket epilogue
//  K2 k_mid  : 1 block: cutoff suffix-scan over 16K bins -> gather -> sort
//              -> decode top-512
//  K3 k_iou  : 128x256: 512x512 suppression bitmask (pure, no join)
//  K4 k_nms  : 1 block: greedy NMS with NAMED-REGISTER diagonal (fixes the
//              LDS-sunk serial chain that cost ~13us) -> output -> reset
// ---------------------------------------------------------------------------

#define NB2      16384              // score-bit bins (128-ulp)
#define BSHIFT   7
#define BASEBITS 0x3F666666u        // bits(0.9f)
#define CAP      128                // per-bin bucket capacity (max seen ~30)
#define KTOP     512
#define SELCAP   1024
#define PREF_T   2.19f              // conservative prefilter: ln(9)=2.1972

__device__ __align__(16) int  g_hist[NB2];
__device__ unsigned long long g_bucket[NB2 * CAP];   // 16MB
__device__ float4             g_box[KTOP];
__device__ float              g_area[KTOP];
__device__ float              g_score[KTOP];
__device__ __align__(16) unsigned g_mask32[KTOP * 16];

// ---------------------------------------------------------------------------
// K1: 256 threads/block, 2048 float4 (4096 priors) per block, grid 512.
// ---------------------------------------------------------------------------
__global__ void __launch_bounds__(256) k_scan(const float4* __restrict__ conf4, int n4) {
    __shared__ unsigned long long lbuf[4096];   // full worst-case coverage (32KB)
    __shared__ int lcount;
    int tid = threadIdx.x;
    if (tid == 0) lcount = 0;
    __syncthreads();

    int base = blockIdx.x * 2048 + tid;
#pragma unroll
    for (int k = 0; k < 8; ++k) {
        int i4 = base + k * 256;
        if (i4 < n4) {
            float4 c = conf4[i4];
            if (c.y - c.x > PREF_T) {                       // rare (~6%)
                float s = 1.0f / (1.0f + expf(c.x - c.y));  // exact fp32 softmax
                if (s > 0.9f) {
                    unsigned idx = 2u * (unsigned)i4;
                    int pos = atomicAdd(&lcount, 1);
                    lbuf[pos] = ((unsigned long long)__float_as_uint(s) << 32) |
                                (unsigned long long)(0xffffffffu - idx);
                }
            }
            if (c.w - c.z > PREF_T) {
                float s = 1.0f / (1.0f + expf(c.z - c.w));
                if (s > 0.9f) {
                    unsigned idx = 2u * (unsigned)i4 + 1u;
                    int pos = atomicAdd(&lcount, 1);
                    lbuf[pos] = ((unsigned long long)__float_as_uint(s) << 32) |
                                (unsigned long long)(0xffffffffu - idx);
                }
            }
        }
    }
    __syncthreads();

    // epilogue: scatter staged keys into score-binned buckets (off stream path)
    int lc = lcount;
    for (int j = tid; j < lc; j += 256) {
        unsigned long long key = lbuf[j];
        int bin  = (int)(((unsigned)(key >> 32) - BASEBITS) >> BSHIFT);
        int slot = atomicAdd(&g_hist[bin], 1);
        if (slot < CAP) g_bucket[bin * CAP + slot] = key;
    }
}

// hybrid bitonic helper (descending, 64-bit keys)
__device__ __forceinline__ unsigned long long bt_shfl(unsigned long long v, int j,
                                                      int k, int tid) {
    unsigned long long pv = __shfl_xor_sync(0xffffffffu, v, j);
    bool ilow   = (tid & j) == 0;
    bool maxlow = (tid & k) == 0;
    return (ilow == maxlow) ? (v > pv ? v : pv) : (v < pv ? v : pv);
}

// ---------------------------------------------------------------------------
// K2: single block of 1024: cutoff -> gather -> sort -> decode.
// ---------------------------------------------------------------------------
__global__ void __launch_bounds__(1024, 1) k_mid(const float4* __restrict__ loc,
                                                 const float4* __restrict__ priors) {
    __shared__ unsigned long long sbuf[SELCAP];
    __shared__ int s_wtot[32], s_wsuf[32];
    __shared__ int s_cut, s_n;
    int tid  = threadIdx.x;
    int lane = tid & 31;
    int wid  = tid >> 5;

    // each thread owns 16 bins [16*tid, 16*tid+16)
    int cnt16[16];
    int part = 0;
#pragma unroll
    for (int q = 0; q < 4; ++q) {
        int4 h = ((const int4*)g_hist)[tid * 4 + q];
        cnt16[q * 4 + 0] = h.x; cnt16[q * 4 + 1] = h.y;
        cnt16[q * 4 + 2] = h.z; cnt16[q * 4 + 3] = h.w;
        part += h.x + h.y + h.z + h.w;
    }
    int suf = part;
#pragma unroll
    for (int s = 1; s < 32; s <<= 1) {
        int t = __shfl_down_sync(0xffffffffu, suf, s);
        if (lane + s < 32) suf += t;
    }
    if (lane == 0) s_wtot[wid] = suf;
    if (tid == 0) { s_cut = 0; s_n = 0; }
    __syncthreads();
    if (wid == 0) {
        int ws = s_wtot[lane];
#pragma unroll
        for (int s = 1; s < 32; s <<= 1) {
            int t = __shfl_down_sync(0xffffffffu, ws, s);
            if (lane + s < 32) ws += t;
        }
        s_wsuf[lane] = ws;
    }
    __syncthreads();
    int S     = suf + ((wid < 31) ? s_wsuf[wid + 1] : 0);
    int Snext = S - part;
    if (S >= KTOP && Snext < KTOP) {
        int run = Snext;
#pragma unroll
        for (int r = 15; r >= 0; --r) {
            run += cnt16[r];
            if (run >= KTOP) { s_cut = tid * 16 + r; break; }
        }
    }
    sbuf[tid] = 0ull;
    __syncthreads();
    int cut = s_cut;

    // gather bins >= cut (order irrelevant, the sort fixes it)
    int cc[16];
    int tc = 0;
#pragma unroll
    for (int r = 0; r < 16; ++r) {
        int b = tid * 16 + r;
        int c = (b >= cut) ? cnt16[r] : 0;
        if (c > CAP) c = CAP;
        cc[r] = c;
        tc += c;
    }
    int off = 0;
    if (tc) off = atomicAdd(&s_n, tc);
#pragma unroll
    for (int r = 0; r < 16; ++r) {
        int b = tid * 16 + r;
        for (int i = 0; i < cc[r]; ++i) {
            if (off < SELCAP) sbuf[off] = g_bucket[b * CAP + i];
            ++off;
        }
    }
    __syncthreads();

    // hybrid bitonic sort (desc) over 1024 keys
    unsigned long long v = sbuf[tid];
#pragma unroll
    for (int k = 2; k <= 32; k <<= 1)
#pragma unroll
        for (int j = k >> 1; j >= 1; j >>= 1)
            v = bt_shfl(v, j, k, tid);
    for (int k = 64; k <= SELCAP; k <<= 1) {
        for (int j = k >> 1; j >= 32; j >>= 1) {
            __syncthreads();
            sbuf[tid] = v;
            __syncthreads();
            unsigned long long pv = sbuf[tid ^ j];
            bool ilow = (tid & j) == 0;
            bool maxlow = (tid & k) == 0;
            v = (ilow == maxlow) ? (v > pv ? v : pv) : (v < pv ? v : pv);
        }
#pragma unroll
        for (int j = 16; j >= 1; j >>= 1)
            v = bt_shfl(v, j, k, tid);
    }

    // decode top-512
    if (tid < KTOP) {
        unsigned long long key = v;
        float X1 = 0.f, Y1 = 0.f, X2 = 0.f, Y2 = 0.f, score = -1.0f;
        if (key != 0ull) {
            score = __uint_as_float((unsigned)(key >> 32));
            unsigned idx = 0xffffffffu - (unsigned)(key & 0xffffffffu);
            float4 l = __ldg(&loc[idx]);
            float4 p = __ldg(&priors[idx]);
            float cx = __fadd_rn(p.x, __fmul_rn(__fmul_rn(l.x, 0.1f), p.z));
            float cy = __fadd_rn(p.y, __fmul_rn(__fmul_rn(l.y, 0.1f), p.w));
            float w  = __fmul_rn(p.z, expf(__fmul_rn(l.z, 0.2f)));
            float h  = __fmul_rn(p.w, expf(__fmul_rn(l.w, 0.2f)));
            float x1 = __fsub_rn(cx, __fmul_rn(w, 0.5f));
            float y1 = __fsub_rn(cy, __fmul_rn(h, 0.5f));
            float x2 = __fadd_rn(x1, w);
            float y2 = __fadd_rn(y1, h);
            X1 = __fmul_rn(x1, 2048.0f);
            Y1 = __fmul_rn(y1, 2048.0f);
            X2 = __fmul_rn(x2, 2048.0f);
            Y2 = __fmul_rn(y2, 2048.0f);
        }
        g_box[tid]   = make_float4(X1, Y1, X2, Y2);
        g_area[tid]  = __fmul_rn(__fadd_rn(__fsub_rn(X2, X1), 1.0f),
                                 __fadd_rn(__fsub_rn(Y2, Y1), 1.0f));
        g_score[tid] = score;
    }
}

// ---------------------------------------------------------------------------
// K3: 512x512 suppression bitmask; no join, launch boundary is the barrier.
// ---------------------------------------------------------------------------
__global__ void __launch_bounds__(256) k_iou() {
    int T  = blockIdx.x * 256 + threadIdx.x;   // 0..32767
    int i  = T >> 6;
    int j0 = (T & 63) << 3;
    unsigned bits = 0u;
    float si = g_score[i];
    if (si > 0.0f) {
        float4 bi = g_box[i];
        float  ai = g_area[i];
#pragma unroll
        for (int b = 0; b < 8; ++b) {
            int j = j0 + b;
            float4 bj = g_box[j];
            float xx1 = fmaxf(bi.x, bj.x);
            float yy1 = fmaxf(bi.y, bj.y);
            float xx2 = fminf(bi.z, bj.z);
            float yy2 = fminf(bi.w, bj.w);
            float w = fmaxf(__fadd_rn(__fsub_rn(xx2, xx1), 1.0f), 0.0f);
            float h = fmaxf(__fadd_rn(__fsub_rn(yy2, yy1), 1.0f), 0.0f);
            float inter = __fmul_rn(w, h);
            float uni = __fsub_rn(__fadd_rn(ai, g_area[j]), inter);
            if (j > i && inter > __fmul_rn(0.4f, uni)) bits |= 1u << b;
        }
    }
    ((unsigned char*)g_mask32)[T] = (unsigned char)bits;
}

// ---------------------------------------------------------------------------
// K4: single block of 512: greedy NMS + output + histogram reset.
// The 32 diagonal words per chunk are loaded into NAMED scalar registers so
// the serial closure chain is pure ALU (prev version let ptxas sink the LDS
// loads into the chain -> 29cyc/step -> 17.8us kernel).
// ---------------------------------------------------------------------------
#define DLOAD(r) unsigned d##r = um[(cb + r) * 16 + c];
#define DSTEP(r) if (!(val & (1u << r))) val |= d##r;
#define REP32(M) M(0) M(1) M(2) M(3) M(4) M(5) M(6) M(7) \
                 M(8) M(9) M(10) M(11) M(12) M(13) M(14) M(15) \
                 M(16) M(17) M(18) M(19) M(20) M(21) M(22) M(23) \
                 M(24) M(25) M(26) M(27) M(28) M(29) M(30) M(31)

__global__ void __launch_bounds__(512, 1) k_nms(float* __restrict__ out) {
    __shared__ unsigned um[KTOP * 16];    // 32KB suppression matrix
    __shared__ unsigned s_keepw[16];
    int tid = threadIdx.x;
    for (int w = tid; w < KTOP * 4; w += 512)
        ((uint4*)um)[w] = ((const uint4*)g_mask32)[w];
    __syncthreads();

    if (tid < 32) {
        int wlo = tid & 15;               // lanes 0..15 own column words
        unsigned rem = 0u;
        for (int c = 0; c < 16; ++c) {
            unsigned val = __shfl_sync(0xffffffffu, rem, c);
            int cb = c * 32;
            // load chunk diagonal into 32 NAMED registers (independent LDS)
            REP32(DLOAD)
            // intra-chunk 32-step closure: pure ALU dependent chain
            REP32(DSTEP)
            unsigned keep = ~val;
            // cross-chunk: 32 independent LDS + predicated OR accumulate
            unsigned acc = 0u;
#pragma unroll
            for (int r = 0; r < 32; ++r) {
                unsigned m = um[(cb + r) * 16 + wlo];
                acc |= ((keep >> r) & 1u) ? m : 0u;
            }
            if (tid < 16) rem |= acc;
        }
        if (tid < 16) s_keepw[tid] = rem;
    }
    __syncthreads();

    const float inv = 1.0f / 2048.0f;     // exact
    if (tid < KTOP) {
        int r = tid;
        float sc = g_score[r];
        bool kept = (sc > 0.0f) && !((s_keepw[r >> 5] >> (r & 31)) & 1u);
        float4 b = g_box[r];
        out[r * 5 + 0] = kept ? __fmul_rn(b.x, inv) : 0.0f;
        out[r * 5 + 1] = kept ? __fmul_rn(b.y, inv) : 0.0f;
        out[r * 5 + 2] = kept ? __fmul_rn(b.z, inv) : 0.0f;
        out[r * 5 + 3] = kept ? __fmul_rn(b.w, inv) : 0.0f;
        out[r * 5 + 4] = kept ? sc : 0.0f;
    }

    // histogram reset for the next graph replay (zero-initialized at load)
    for (int i = tid; i < NB2; i += 512) g_hist[i] = 0;
}

// ---------------------------------------------------------------------------
extern "C" void kernel_launch(void* const* d_in, const int* in_sizes, int n_in,
                              void* d_out, int out_size) {
    const float4* loc    = (const float4*)d_in[0];   // [N,4]
    const float4* conf4  = (const float4*)d_in[1];   // [N,2] as float4 pairs
    const float4* priors = (const float4*)d_in[2];   // [N,4]
    float* out = (float*)d_out;                      // [512,5]
    int n  = in_sizes[0] / 4;
    int n4 = n >> 1;

    k_scan<<<(n4 + 2047) / 2048, 256>>>(conf4, n4);
    k_mid<<<1, 1024>>>(loc, priors);
    k_iou<<<128, 256>>>();
    k_nms<<<1, 512>>>(out);
}

// round 10
// speedup vs baseline: 1.8573x; 1.0998x over previous
#include <cuda_runtime.h>

// ---------------------------------------------------------------------------
// SSD post-process, 4 lean kernels (launch boundaries = barriers, no fences):
//  K1 k_scan : stream conf (batched loads, branchy prefilter, shared staging,
//              bucket epilogue)
//  K2 k_mid  : 1 block: cutoff suffix-scan over 16K bins -> gather -> sort
//              -> decode top-512
//  K3 k_iou  : 128x256: 512x512 suppression bitmask (pure, no join)
//  K4 k_nms  : 1 block: greedy NMS; chunk diagonal distributed via SHFL into
//              registers (un-sinkable), branch-free closure steps -> output
//              -> histogram reset
// ---------------------------------------------------------------------------

#define NB2      16384              // score-bit bins (128-ulp)
#define BSHIFT   7
#define BASEBITS 0x3F666666u        // bits(0.9f)
#define CAP      128                // per-bin bucket capacity (max seen ~30)
#define KTOP     512
#define SELCAP   1024
#define PREF_T   2.19f              // conservative prefilter: ln(9)=2.1972

__device__ __align__(16) int  g_hist[NB2];
__device__ unsigned long long g_bucket[NB2 * CAP];   // 16MB
__device__ float4             g_box[KTOP];
__device__ float              g_area[KTOP];
__device__ float              g_score[KTOP];
__device__ __align__(16) unsigned g_mask32[KTOP * 16];

// ---------------------------------------------------------------------------
// K1: 256 threads/block, 1024 float4 (2048 priors) per block, grid 1024.
// ---------------------------------------------------------------------------
__global__ void __launch_bounds__(256) k_scan(const float4* __restrict__ conf4, int n4) {
    __shared__ unsigned long long lbuf[2048];   // worst-case coverage (16KB)
    __shared__ int lcount;
    int tid = threadIdx.x;
    if (tid == 0) lcount = 0;
    __syncthreads();

    int base = blockIdx.x * 1024 + tid;
    float4 v[4];
#pragma unroll
    for (int k = 0; k < 4; ++k) {
        int i4 = base + k * 256;
        v[k] = (i4 < n4) ? conf4[i4] : make_float4(0.f, 0.f, 0.f, 0.f);
    }
#pragma unroll
    for (int k = 0; k < 4; ++k) {
        int i4 = base + k * 256;
        if (v[k].y - v[k].x > PREF_T) {                     // rare (~3%)
            float s = 1.0f / (1.0f + expf(v[k].x - v[k].y)); // exact fp32 softmax
            if (s > 0.9f) {
                unsigned idx = 2u * (unsigned)i4;
                int pos = atomicAdd(&lcount, 1);
                lbuf[pos] = ((unsigned long long)__float_as_uint(s) << 32) |
                            (unsigned long long)(0xffffffffu - idx);
            }
        }
        if (v[k].w - v[k].z > PREF_T) {
            float s = 1.0f / (1.0f + expf(v[k].z - v[k].w));
            if (s > 0.9f) {
                unsigned idx = 2u * (unsigned)i4 + 1u;
                int pos = atomicAdd(&lcount, 1);
                lbuf[pos] = ((unsigned long long)__float_as_uint(s) << 32) |
                            (unsigned long long)(0xffffffffu - idx);
            }
        }
    }
    __syncthreads();

    // epilogue: scatter staged keys into score-binned buckets (off stream path)
    int lc = lcount;
    for (int j = tid; j < lc; j += 256) {
        unsigned long long key = lbuf[j];
        int bin  = (int)(((unsigned)(key >> 32) - BASEBITS) >> BSHIFT);
        int slot = atomicAdd(&g_hist[bin], 1);
        if (slot < CAP) g_bucket[bin * CAP + slot] = key;
    }
}

// hybrid bitonic helper (descending, 64-bit keys)
__device__ __forceinline__ unsigned long long bt_shfl(unsigned long long v, int j,
                                                      int k, int tid) {
    unsigned long long pv = __shfl_xor_sync(0xffffffffu, v, j);
    bool ilow   = (tid & j) == 0;
    bool maxlow = (tid & k) == 0;
    return (ilow == maxlow) ? (v > pv ? v : pv) : (v < pv ? v : pv);
}

// ---------------------------------------------------------------------------
// K2: single block of 1024: cutoff -> gather -> sort -> decode.
// ---------------------------------------------------------------------------
__global__ void __launch_bounds__(1024, 1) k_mid(const float4* __restrict__ loc,
                                                 const float4* __restrict__ priors) {
    __shared__ unsigned long long sbuf[SELCAP];
    __shared__ int s_wtot[32], s_wsuf[32];
    __shared__ int s_cut, s_n;
    int tid  = threadIdx.x;
    int lane = tid & 31;
    int wid  = tid >> 5;

    // each thread owns 16 bins [16*tid, 16*tid+16)
    int cnt16[16];
    int part = 0;
#pragma unroll
    for (int q = 0; q < 4; ++q) {
        int4 h = ((const int4*)g_hist)[tid * 4 + q];
        cnt16[q * 4 + 0] = h.x; cnt16[q * 4 + 1] = h.y;
        cnt16[q * 4 + 2] = h.z; cnt16[q * 4 + 3] = h.w;
        part += h.x + h.y + h.z + h.w;
    }
    int suf = part;
#pragma unroll
    for (int s = 1; s < 32; s <<= 1) {
        int t = __shfl_down_sync(0xffffffffu, suf, s);
        if (lane + s < 32) suf += t;
    }
    if (lane == 0) s_wtot[wid] = suf;
    if (tid == 0) { s_cut = 0; s_n = 0; }
    __syncthreads();
    if (wid == 0) {
        int ws = s_wtot[lane];
#pragma unroll
        for (int s = 1; s < 32; s <<= 1) {
            int t = __shfl_down_sync(0xffffffffu, ws, s);
            if (lane + s < 32) ws += t;
        }
        s_wsuf[lane] = ws;
    }
    __syncthreads();
    int S     = suf + ((wid < 31) ? s_wsuf[wid + 1] : 0);
    int Snext = S - part;
    if (S >= KTOP && Snext < KTOP) {
        int run = Snext;
#pragma unroll
        for (int r = 15; r >= 0; --r) {
            run += cnt16[r];
            if (run >= KTOP) { s_cut = tid * 16 + r; break; }
        }
    }
    sbuf[tid] = 0ull;
    __syncthreads();
    int cut = s_cut;

    // gather bins >= cut (order irrelevant, the sort fixes it)
    int cc[16];
    int tc = 0;
#pragma unroll
    for (int r = 0; r < 16; ++r) {
        int b = tid * 16 + r;
        int c = (b >= cut) ? cnt16[r] : 0;
        if (c > CAP) c = CAP;
        cc[r] = c;
        tc += c;
    }
    int off = 0;
    if (tc) off = atomicAdd(&s_n, tc);
#pragma unroll
    for (int r = 0; r < 16; ++r) {
        int b = tid * 16 + r;
        for (int i = 0; i < cc[r]; ++i) {
            if (off < SELCAP) sbuf[off] = g_bucket[b * CAP + i];
            ++off;
        }
    }
    __syncthreads();

    // hybrid bitonic sort (desc) over 1024 keys
    unsigned long long v = sbuf[tid];
#pragma unroll
    for (int k = 2; k <= 32; k <<= 1)
#pragma unroll
        for (int j = k >> 1; j >= 1; j >>= 1)
            v = bt_shfl(v, j, k, tid);
    for (int k = 64; k <= SELCAP; k <<= 1) {
        for (int j = k >> 1; j >= 32; j >>= 1) {
            __syncthreads();
            sbuf[tid] = v;
            __syncthreads();
            unsigned long long pv = sbuf[tid ^ j];
            bool ilow = (tid & j) == 0;
            bool maxlow = (tid & k) == 0;
            v = (ilow == maxlow) ? (v > pv ? v : pv) : (v < pv ? v : pv);
        }
#pragma unroll
        for (int j = 16; j >= 1; j >>= 1)
            v = bt_shfl(v, j, k, tid);
    }

    // decode top-512
    if (tid < KTOP) {
        unsigned long long key = v;
        float X1 = 0.f, Y1 = 0.f, X2 = 0.f, Y2 = 0.f, score = -1.0f;
        if (key != 0ull) {
            score = __uint_as_float((unsigned)(key >> 32));
            unsigned idx = 0xffffffffu - (unsigned)(key & 0xffffffffu);
            float4 l = __ldg(&loc[idx]);
            float4 p = __ldg(&priors[idx]);
            float cx = __fadd_rn(p.x, __fmul_rn(__fmul_rn(l.x, 0.1f), p.z));
            float cy = __fadd_rn(p.y, __fmul_rn(__fmul_rn(l.y, 0.1f), p.w));
            float w  = __fmul_rn(p.z, expf(__fmul_rn(l.z, 0.2f)));
            float h  = __fmul_rn(p.w, expf(__fmul_rn(l.w, 0.2f)));
            float x1 = __fsub_rn(cx, __fmul_rn(w, 0.5f));
            float y1 = __fsub_rn(cy, __fmul_rn(h, 0.5f));
            float x2 = __fadd_rn(x1, w);
            float y2 = __fadd_rn(y1, h);
            X1 = __fmul_rn(x1, 2048.0f);
            Y1 = __fmul_rn(y1, 2048.0f);
            X2 = __fmul_rn(x2, 2048.0f);
            Y2 = __fmul_rn(y2, 2048.0f);
        }
        g_box[tid]   = make_float4(X1, Y1, X2, Y2);
        g_area[tid]  = __fmul_rn(__fadd_rn(__fsub_rn(X2, X1), 1.0f),
                                 __fadd_rn(__fsub_rn(Y2, Y1), 1.0f));
        g_score[tid] = score;
    }
}

// ---------------------------------------------------------------------------
// K3: 512x512 suppression bitmask; no join, launch boundary is the barrier.
// ---------------------------------------------------------------------------
__global__ void __launch_bounds__(256) k_iou() {
    int T  = blockIdx.x * 256 + threadIdx.x;   // 0..32767
    int i  = T >> 6;
    int j0 = (T & 63) << 3;
    unsigned bits = 0u;
    float si = g_score[i];
    if (si > 0.0f) {
        float4 bi = g_box[i];
        float  ai = g_area[i];
#pragma unroll
        for (int b = 0; b < 8; ++b) {
            int j = j0 + b;
            float4 bj = g_box[j];
            float xx1 = fmaxf(bi.x, bj.x);
            float yy1 = fmaxf(bi.y, bj.y);
            float xx2 = fminf(bi.z, bj.z);
            float yy2 = fminf(bi.w, bj.w);
            float w = fmaxf(__fadd_rn(__fsub_rn(xx2, xx1), 1.0f), 0.0f);
            float h = fmaxf(__fadd_rn(__fsub_rn(yy2, yy1), 1.0f), 0.0f);
            float inter = __fmul_rn(w, h);
            float uni = __fsub_rn(__fadd_rn(ai, g_area[j]), inter);
            if (j > i && inter > __fmul_rn(0.4f, uni)) bits |= 1u << b;
        }
    }
    ((unsigned char*)g_mask32)[T] = (unsigned char)bits;
}

// ---------------------------------------------------------------------------
// K4: single block of 512: greedy NMS + output + histogram reset.
// Chunk diagonal: lane r does ONE LDS, values distributed via __shfl into
// named registers (shfl results cannot be sunk into loads by ptxas).
// Closure step is branch-free: sign-broadcast of bit r gates the OR (LOP3).
// ---------------------------------------------------------------------------
#define DSH(r)  unsigned d##r = __shfl_sync(0xffffffffu, D, r);
#define DST(r)  { unsigned sgn = (unsigned)(((int)(val << (31 - (r)))) >> 31); \
                  val = val | (d##r & ~sgn); }
#define REP32(M) M(0) M(1) M(2) M(3) M(4) M(5) M(6) M(7) \
                 M(8) M(9) M(10) M(11) M(12) M(13) M(14) M(15) \
                 M(16) M(17) M(18) M(19) M(20) M(21) M(22) M(23) \
                 M(24) M(25) M(26) M(27) M(28) M(29) M(30) M(31)

__global__ void __launch_bounds__(512, 1) k_nms(float* __restrict__ out) {
    __shared__ unsigned um[KTOP * 16];    // 32KB suppression matrix
    __shared__ unsigned s_keepw[16];
    int tid = threadIdx.x;
    for (int w = tid; w < KTOP * 4; w += 512)
        ((uint4*)um)[w] = ((const uint4*)g_mask32)[w];
    __syncthreads();

    if (tid < 32) {
        int lane = tid;
        int wlo  = lane & 15;             // lanes 0..15 own column words
        unsigned rem = 0u;
        for (int c = 0; c < 16; ++c) {
            unsigned val = __shfl_sync(0xffffffffu, rem, c);
            int cb = c * 32;
            // one LDS per lane: the chunk's diagonal word for row cb+lane
            unsigned D = um[(cb + lane) * 16 + c];
            // distribute into 32 named registers via shfl (un-sinkable)
            REP32(DSH)
            // 32-step serial closure: pure ALU (SHL+SAR+LOP3 per step)
            REP32(DST)
            unsigned keep = ~val;
            // cross-chunk: 4 independent accumulators, conflict-free LDS
            unsigned a0 = 0u, a1 = 0u, a2 = 0u, a3 = 0u;
#pragma unroll
            for (int r = 0; r < 32; r += 4) {
                unsigned m0 = um[(cb + r + 0) * 16 + wlo];
                unsigned m1 = um[(cb + r + 1) * 16 + wlo];
                unsigned m2 = um[(cb + r + 2) * 16 + wlo];
                unsigned m3 = um[(cb + r + 3) * 16 + wlo];
                a0 |= ((keep >> (r + 0)) & 1u) ? m0 : 0u;
                a1 |= ((keep >> (r + 1)) & 1u) ? m1 : 0u;
                a2 |= ((keep >> (r + 2)) & 1u) ? m2 : 0u;
                a3 |= ((keep >> (r + 3)) & 1u) ? m3 : 0u;
            }
            if (lane < 16) rem |= (a0 | a1) | (a2 | a3);
        }
        if (tid < 16) s_keepw[tid] = rem;
    }
    __syncthreads();

    const float inv = 1.0f / 2048.0f;     // exact
    if (tid < KTOP) {
        int r = tid;
        float sc = g_score[r];
        bool kept = (sc > 0.0f) && !((s_keepw[r >> 5] >> (r & 31)) & 1u);
        float4 b = g_box[r];
        out[r * 5 + 0] = kept ? __fmul_rn(b.x, inv) : 0.0f;
        out[r * 5 + 1] = kept ? __fmul_rn(b.y, inv) : 0.0f;
        out[r * 5 + 2] = kept ? __fmul_rn(b.z, inv) : 0.0f;
        out[r * 5 + 3] = kept ? __fmul_rn(b.w, inv) : 0.0f;
        out[r * 5 + 4] = kept ? sc : 0.0f;
    }

    // histogram reset for the next graph replay (zero-initialized at load)
    for (int i = tid; i < NB2; i += 512) g_hist[i] = 0;
}

// ---------------------------------------------------------------------------
extern "C" void kernel_launch(void* const* d_in, const int* in_sizes, int n_in,
                              void* d_out, int out_size) {
    const float4* loc    = (const float4*)d_in[0];   // [N,4]
    const float4* conf4  = (const float4*)d_in[1];   // [N,2] as float4 pairs
    const float4* priors = (const float4*)d_in[2];   // [N,4]
    float* out = (float*)d_out;                      // [512,5]
    int n  = in_sizes[0] / 4;
    int n4 = n >> 1;

    k_scan<<<(n4 + 1023) / 1024, 256>>>(conf4, n4);
    k_mid<<<1, 1024>>>(loc, priors);
    k_iou<<<128, 256>>>();
    k_nms<<<1, 512>>>(out);
}